// round 6
// baseline (speedup 1.0000x reference)
#include <cuda_runtime.h>
#include <cuda_fp16.h>
#include <stdint.h>

// Problem constants
#define NPLANES 32            // B*C = 2*16
#define NTEX    512
#define HT      64
#define WT      64
#define TEXELS  (NTEX*HT*WT)  // 2,097,152 texels; plane stride in x
#define HO      1024
#define WO      1024
#define NPIX    (HO*WO)

#define TILE_T  256           // texels per transpose tile

// 128 MB transposed fp16 atlas: g_xt_h[texel][channel]; one texel's 32
// channels = one 64B half-line (16 half2).
__device__ __half g_xt_h[(size_t)TEXELS * NPLANES];

// ---------------------------------------------------------------------------
// Pass 1: transpose + fp32->fp16, 32 planes x 256 texels per block
// (unchanged from R5; 71us at the ~5.4TB/s streaming ceiling).
// ---------------------------------------------------------------------------
__global__ __launch_bounds__(1024) void transpose_kernel(const float* __restrict__ x) {
    __shared__ float tile[32][TILE_T + 1];
    const int w    = threadIdx.x >> 5;
    const int lane = threadIdx.x & 31;
    const int tbase = blockIdx.x * TILE_T;

    const float4* src4 = (const float4*)(x + (size_t)w * TEXELS + tbase);
    const float4 a = src4[lane];
    const float4 b = src4[32 + lane];
    {
        const int t0 = lane * 4;
        tile[w][t0 + 0] = a.x; tile[w][t0 + 1] = a.y;
        tile[w][t0 + 2] = a.z; tile[w][t0 + 3] = a.w;
        const int t1 = (32 + lane) * 4;
        tile[w][t1 + 0] = b.x; tile[w][t1 + 1] = b.y;
        tile[w][t1 + 2] = b.z; tile[w][t1 + 3] = b.w;
    }
    __syncthreads();

    const int tq = lane >> 3;
    const int c  = lane & 7;
    #pragma unroll
    for (int j = 0; j < 2; j++) {
        const int t = w * 8 + j * 4 + tq;
        const float v0 = tile[4 * c + 0][t];
        const float v1 = tile[4 * c + 1][t];
        const float v2 = tile[4 * c + 2][t];
        const float v3 = tile[4 * c + 3][t];
        const __half2 h0 = __floats2half2_rn(v0, v1);
        const __half2 h1 = __floats2half2_rn(v2, v3);
        uint2 pk;
        pk.x = *(const unsigned int*)&h0;
        pk.y = *(const unsigned int*)&h1;
        *(uint2*)(g_xt_h + (size_t)(tbase + t) * NPLANES + 4 * c) = pk;
    }
}

// ---------------------------------------------------------------------------
// Pass 2: 2 pixels per warp per iteration via half2 lanes, with the block's
// qidx/uv prefetched into smem so the corner-gather address path has no
// global-load dependency (deeper effective MLP on the 16 corner LDGs).
// ---------------------------------------------------------------------------
__global__ __launch_bounds__(256) void sample_kernel(
    const int*    __restrict__ qidx,
    const float2* __restrict__ uv,
    float*        __restrict__ out) {

    __shared__ float  s[64][33];
    __shared__ int    s_base[64];   // precomputed texel row base n*HT*WT
    __shared__ float2 s_uv[64];

    const int tid  = threadIdx.x;
    const int w    = tid >> 5;
    const int lane = tid & 31;
    const int half = lane >> 4;
    const int j    = lane & 15;
    const int pixbase = blockIdx.x * 64;

    // Cooperative prefetch of per-pixel params (coalesced, one shot).
    if (tid < 64) {
        int n = __ldcs(&qidx[pixbase + tid]);
        n = min(max(n, 0), NTEX - 1);
        s_base[tid] = n * (HT * WT);
        s_uv[tid]   = __ldcs(&uv[pixbase + tid]);
    }
    __syncthreads();

    const __half2* atlas = (const __half2*)g_xt_h;

    #pragma unroll
    for (int i = 0; i < 4; i++) {
        const int pl = w * 8 + i * 2 + half;

        const int    rbase = s_base[pl];     // broadcast LDS
        const float2 t     = s_uv[pl];
        const float  u  = t.x * 63.0f;
        const float  v  = t.y * 63.0f;
        const float  x0f = floorf(u);
        const float  y0f = floorf(v);
        const float  wu  = u - x0f;
        const float  wv  = v - y0f;

        int x0 = (int)x0f; x0 = min(max(x0, 0), WT - 1);
        int y0 = (int)y0f; y0 = min(max(y0, 0), HT - 1);
        const int x1 = min(x0 + 1, WT - 1);
        const int y1 = min(y0 + 1, HT - 1);

        const int r0 = rbase + y0 * WT;
        const int r1 = rbase + y1 * WT;

        const float2 g00 = __half22float2(atlas[(size_t)(r0 + x0) * 16 + j]);
        const float2 g01 = __half22float2(atlas[(size_t)(r0 + x1) * 16 + j]);
        const float2 g10 = __half22float2(atlas[(size_t)(r1 + x0) * 16 + j]);
        const float2 g11 = __half22float2(atlas[(size_t)(r1 + x1) * 16 + j]);

        const float topx = fmaf(wu, g01.x - g00.x, g00.x);
        const float botx = fmaf(wu, g11.x - g10.x, g10.x);
        const float topy = fmaf(wu, g01.y - g00.y, g00.y);
        const float boty = fmaf(wu, g11.y - g10.y, g10.y);

        s[pl][2 * j]     = fmaf(wv, botx - topx, topx);
        s[pl][2 * j + 1] = fmaf(wv, boty - topy, topy);
    }

    __syncthreads();

    #pragma unroll
    for (int jj = 0; jj < 4; jj++) {
        const int p = w * 4 + jj;
        float* o = out + (size_t)p * NPIX + pixbase;
        __stwt(&o[lane],      s[lane][p]);
        __stwt(&o[32 + lane], s[32 + lane][p]);
    }
}

extern "C" void kernel_launch(void* const* d_in, const int* in_sizes, int n_in,
                              void* d_out, int out_size) {
    const float*  x    = (const float*)d_in[0];
    const int*    qidx = (const int*)d_in[1];
    const float2* uv   = (const float2*)d_in[2];
    float*        out  = (float*)d_out;

    transpose_kernel<<<TEXELS / TILE_T, 1024>>>(x);
    sample_kernel<<<NPIX / 64, 256>>>(qidx, uv, out);
}

// round 7
// speedup vs baseline: 1.0383x; 1.0383x over previous
#include <cuda_runtime.h>
#include <cuda_fp16.h>
#include <stdint.h>

// Problem constants
#define NPLANES 32            // B*C = 2*16
#define NTEX    512
#define HT      64
#define WT      64
#define TEXELS  (NTEX*HT*WT)  // 2,097,152 texels; plane stride in x
#define HO      1024
#define WO      1024
#define NPIX    (HO*WO)

#define TILE_T  256           // texels per transpose tile

// 128 MB transposed fp16 atlas: g_xt_h[texel][channel]; one texel's 32
// channels = one 64B half-line (16 half2).
__device__ __half g_xt_h[(size_t)TEXELS * NPLANES];

// ---------------------------------------------------------------------------
// Pass 1: transpose + fp32->fp16, 32 planes x 256 texels per block
// (unchanged; ~71us at the ~5.4TB/s streaming ceiling).
// ---------------------------------------------------------------------------
__global__ __launch_bounds__(1024) void transpose_kernel(const float* __restrict__ x) {
    __shared__ float tile[32][TILE_T + 1];
    const int w    = threadIdx.x >> 5;
    const int lane = threadIdx.x & 31;
    const int tbase = blockIdx.x * TILE_T;

    const float4* src4 = (const float4*)(x + (size_t)w * TEXELS + tbase);
    const float4 a = src4[lane];
    const float4 b = src4[32 + lane];
    {
        const int t0 = lane * 4;
        tile[w][t0 + 0] = a.x; tile[w][t0 + 1] = a.y;
        tile[w][t0 + 2] = a.z; tile[w][t0 + 3] = a.w;
        const int t1 = (32 + lane) * 4;
        tile[w][t1 + 0] = b.x; tile[w][t1 + 1] = b.y;
        tile[w][t1 + 2] = b.z; tile[w][t1 + 3] = b.w;
    }
    __syncthreads();

    const int tq = lane >> 3;
    const int c  = lane & 7;
    #pragma unroll
    for (int j = 0; j < 2; j++) {
        const int t = w * 8 + j * 4 + tq;
        const float v0 = tile[4 * c + 0][t];
        const float v1 = tile[4 * c + 1][t];
        const float v2 = tile[4 * c + 2][t];
        const float v3 = tile[4 * c + 3][t];
        const __half2 h0 = __floats2half2_rn(v0, v1);
        const __half2 h1 = __floats2half2_rn(v2, v3);
        uint2 pk;
        pk.x = *(const unsigned int*)&h0;
        pk.y = *(const unsigned int*)&h1;
        *(uint2*)(g_xt_h + (size_t)(tbase + t) * NPLANES + 4 * c) = pk;
    }
}

// ---------------------------------------------------------------------------
// Pass 2: 2 pixels per warp per iteration via half2 lanes.
// Register-pipelined: all 4 iterations' qidx/uv broadcast loads issue in a
// prologue (8 independent LDGs), so the 16 corner LDGs have no global load
// in their dependence chain and can be front-batched. No extra barriers.
// ---------------------------------------------------------------------------
__global__ __launch_bounds__(256) void sample_kernel(
    const int*    __restrict__ qidx,
    const float2* __restrict__ uv,
    float*        __restrict__ out) {

    __shared__ float s[64][33];
    const int w    = threadIdx.x >> 5;
    const int lane = threadIdx.x & 31;
    const int half = lane >> 4;
    const int j    = lane & 15;
    const int pixbase = blockIdx.x * 64;

    const __half2* atlas = (const __half2*)g_xt_h;

    // Prologue: load all per-pixel params into registers (independent LDGs).
    int    rn[4];
    float2 ruv[4];
    #pragma unroll
    for (int i = 0; i < 4; i++) {
        const int pix = pixbase + w * 8 + i * 2 + half;
        rn[i]  = __ldcs(&qidx[pix]);
        ruv[i] = __ldcs(&uv[pix]);
    }

    #pragma unroll
    for (int i = 0; i < 4; i++) {
        const int pl = w * 8 + i * 2 + half;

        int n = min(max(rn[i], 0), NTEX - 1);
        const float2 t = ruv[i];
        const float  u  = t.x * 63.0f;
        const float  v  = t.y * 63.0f;
        const float  x0f = floorf(u);
        const float  y0f = floorf(v);
        const float  wu  = u - x0f;
        const float  wv  = v - y0f;

        int x0 = (int)x0f; x0 = min(max(x0, 0), WT - 1);
        int y0 = (int)y0f; y0 = min(max(y0, 0), HT - 1);
        const int x1 = min(x0 + 1, WT - 1);
        const int y1 = min(y0 + 1, HT - 1);

        const int rb = n * (HT * WT);
        const int r0 = rb + y0 * WT;
        const int r1 = rb + y1 * WT;

        const float2 g00 = __half22float2(atlas[(size_t)(r0 + x0) * 16 + j]);
        const float2 g01 = __half22float2(atlas[(size_t)(r0 + x1) * 16 + j]);
        const float2 g10 = __half22float2(atlas[(size_t)(r1 + x0) * 16 + j]);
        const float2 g11 = __half22float2(atlas[(size_t)(r1 + x1) * 16 + j]);

        const float topx = fmaf(wu, g01.x - g00.x, g00.x);
        const float botx = fmaf(wu, g11.x - g10.x, g10.x);
        const float topy = fmaf(wu, g01.y - g00.y, g00.y);
        const float boty = fmaf(wu, g11.y - g10.y, g10.y);

        s[pl][2 * j]     = fmaf(wv, botx - topx, topx);
        s[pl][2 * j + 1] = fmaf(wv, boty - topy, topy);
    }

    __syncthreads();

    #pragma unroll
    for (int jj = 0; jj < 4; jj++) {
        const int p = w * 4 + jj;
        float* o = out + (size_t)p * NPIX + pixbase;
        __stwt(&o[lane],      s[lane][p]);
        __stwt(&o[32 + lane], s[32 + lane][p]);
    }
}

extern "C" void kernel_launch(void* const* d_in, const int* in_sizes, int n_in,
                              void* d_out, int out_size) {
    const float*  x    = (const float*)d_in[0];
    const int*    qidx = (const int*)d_in[1];
    const float2* uv   = (const float2*)d_in[2];
    float*        out  = (float*)d_out;

    transpose_kernel<<<TEXELS / TILE_T, 1024>>>(x);
    sample_kernel<<<NPIX / 64, 256>>>(qidx, uv, out);
}